// round 5
// baseline (speedup 1.0000x reference)
#include <cuda_runtime.h>
#include <cstdint>

#define NQ     8192
#define NR     16384
#define KNN    8
#define NCHUNK 4
#define RPC    (NR / NCHUNK)           // 4096 refs per chunk
#define QPB    128                     // threads (=queries) per phase-1 block
#define QBLK   (NQ / QPB)              // 64 query-blocks
#define REFRESH 64

__device__ float4             g_ref4[NR];                          // 256 KB
__device__ unsigned           g_thr[NQ];                           // shared thresholds (ord space)
__device__ unsigned long long g_cand[(size_t)NQ * NCHUNK * KNN];   // 2 MB

__device__ __forceinline__ unsigned f2ord(float f) {
    unsigned b = __float_as_uint(f);
    return (b & 0x80000000u) ? ~b : (b | 0x80000000u);
}
__device__ __forceinline__ float ord2f(unsigned o) {
    unsigned b = (o & 0x80000000u) ? (o ^ 0x80000000u) : ~o;
    return __uint_as_float(b);
}

// Kernel A: pack reference into {x,y,z,r^2}; also init per-query shared thresholds.
__global__ void knn_pack(const float* __restrict__ ref) {
    int i = blockIdx.x * blockDim.x + threadIdx.x;
    if (i < NQ) g_thr[i] = 0xFFFFFFFFu;          // +inf in ord space
    if (i >= NR) return;
    float x = ref[i * 3 + 0], y = ref[i * 3 + 1], z = ref[i * 3 + 2];
    float rsq = __fadd_rn(__fadd_rn(__fmul_rn(x, x), __fmul_rn(y, y)),
                          __fmul_rn(z, z));
    g_ref4[i] = make_float4(x, y, z, rsq);
}

// Kernel B: thread-per-query over one ref chunk, FFMA proxy distance,
// warp-uniform guarded sorted-8 insert, cross-chunk threshold sharing.
__global__ __launch_bounds__(QPB) void knn_p1(const float* __restrict__ qry) {
    const int qi    = (blockIdx.x % QBLK) * QPB + threadIdx.x;
    const int chunk = blockIdx.x / QBLK;
    const int rbase = chunk * RPC;

    const float qx = qry[qi * 3 + 0];
    const float qy = qry[qi * 3 + 1];
    const float qz = qry[qi * 3 + 2];
    const float m2x = -2.0f * qx, m2y = -2.0f * qy, m2z = -2.0f * qz;

    const float INF = __int_as_float(0x7f800000);
    float bd[KNN];
    int   bi[KNN];
#pragma unroll
    for (int j = 0; j < KNN; ++j) { bd[j] = INF; bi[j] = 0x7fffffff; }

    float sth = INF;

    for (int base = 0; base < RPC; base += REFRESH) {
        // Refresh gate from the cross-chunk shared threshold (L2-fresh load).
        sth = fminf(bd[KNN - 1], ord2f(__ldcg(&g_thr[qi])));

#pragma unroll 8
        for (int i = 0; i < REFRESH; ++i) {
            const int ri = rbase + base + i;
            float4 r = g_ref4[ri];                 // warp-uniform -> broadcast, L1-hot
            // proxy s = r^2 - 2*(q . r): same per-query ordering as full distance
            float s = __fmaf_rn(m2z, r.z, r.w);
            s = __fmaf_rn(m2y, r.y, s);
            s = __fmaf_rn(m2x, r.x, s);

            bool p = (s <= sth);                   // <= : gate may equal true 8th value
            if (__any_sync(0xffffffffu, p)) {      // warp-uniform branch
                float cd = p ? s : INF;            // non-inserting lanes: no-op value
                int   ci = ri;
#pragma unroll
                for (int j = 0; j < KNN; ++j) {
                    bool w = (cd < bd[j]);         // strict < : stable (low idx wins)
                    float td = bd[j]; int ti = bi[j];
                    bd[j] = w ? cd : bd[j];  bi[j] = w ? ci : bi[j];
                    cd    = w ? td : cd;     ci    = w ? ti : ci;
                }
                sth = fminf(sth, bd[KNN - 1]);
                if (p) atomicMin(&g_thr[qi], f2ord(bd[KNN - 1]));   // publish (no return)
            }
        }
    }

    unsigned long long* out = g_cand + ((size_t)qi * NCHUNK + chunk) * KNN;
#pragma unroll
    for (int j = 0; j < KNN; ++j)
        out[j] = ((unsigned long long)f2ord(bd[j]) << 32) | (unsigned)bi[j];
}

// Kernel C: merge NCHUNK*KNN = 32 candidates per query; emit indices as floats.
__global__ void knn_p2(float* __restrict__ out) {
    int qi = blockIdx.x * blockDim.x + threadIdx.x;
    if (qi >= NQ) return;

    unsigned long long best[KNN];
#pragma unroll
    for (int j = 0; j < KNN; ++j) best[j] = ~0ull;

    const unsigned long long* cand = g_cand + (size_t)qi * NCHUNK * KNN;
    for (int c = 0; c < NCHUNK * KNN; ++c) {
        unsigned long long k = cand[c];
        if (k < best[KNN - 1]) {
#pragma unroll
            for (int j = 0; j < KNN; ++j) {
                if (k < best[j]) { unsigned long long t = best[j]; best[j] = k; k = t; }
            }
        }
    }
#pragma unroll
    for (int j = 0; j < KNN; ++j)
        out[qi * KNN + j] = (float)(int)(best[j] & 0xffffffffu);
}

extern "C" void kernel_launch(void* const* d_in, const int* in_sizes, int n_in,
                              void* d_out, int out_size) {
    (void)n_in; (void)out_size;
    const float* q;
    const float* r;
    if (in_sizes[0] < in_sizes[1]) { q = (const float*)d_in[0]; r = (const float*)d_in[1]; }
    else                           { q = (const float*)d_in[1]; r = (const float*)d_in[0]; }

    knn_pack<<<(NR + 255) / 256, 256>>>(r);
    knn_p1<<<QBLK * NCHUNK, QPB>>>(q);
    knn_p2<<<(NQ + 255) / 256, 256>>>((float*)d_out);
}